// round 1
// baseline (speedup 1.0000x reference)
#include <cuda_runtime.h>

// ---------------------------------------------------------------------------
// PolyActGCN: 3x (GCNConv -> BN -> poly) with CSR-based atomic-free gather.
//   Reorder (exact by linearity): conv(x) = segsum(x[col]*ew) @ W + b
// Pipeline per launch:
//   zero -> degree count -> scan (CSR offsets) -> CSR fill
//   [agg -> gemm(f32x2) -> stats -> bnfinalize -> bn+poly] x2
//   agg -> gemm -> d_out
// ---------------------------------------------------------------------------

#define NMAX 131072
#define EMAX 2097152

__device__ float g_agg[(size_t)NMAX * 128];
__device__ float g_act[(size_t)NMAX * 128];
__device__ int   g_deg[NMAX];
__device__ int   g_cur[NMAX];
__device__ int   g_off[NMAX + 1];
__device__ int   g_ccol[EMAX];
__device__ float g_cw[EMAX];
__device__ float g_stats[512];   // sum1[128], ss1[128], sum2[128], ss2[128]
__device__ float g_scale[128];
__device__ float g_shift[128];

// ---------------- f32x2 helpers (Blackwell packed fp32) --------------------
static __device__ __forceinline__ unsigned long long pack2(float x, float y) {
    unsigned long long p;
    asm("mov.b64 %0, {%1, %2};" : "=l"(p)
        : "r"(__float_as_uint(x)), "r"(__float_as_uint(y)));
    return p;
}
static __device__ __forceinline__ float2 unpack2(unsigned long long p) {
    unsigned int a, b;
    asm("mov.b64 {%0, %1}, %2;" : "=r"(a), "=r"(b) : "l"(p));
    return make_float2(__uint_as_float(a), __uint_as_float(b));
}
static __device__ __forceinline__ unsigned long long ffma2(
    unsigned long long a, unsigned long long b, unsigned long long c) {
    unsigned long long d;
    asm("fma.rn.f32x2 %0, %1, %2, %3;" : "=l"(d) : "l"(a), "l"(b), "l"(c));
    return d;
}

// ---------------- CSR build -----------------------------------------------
__global__ void k_zero(int N) {
    int i = blockIdx.x * 256 + threadIdx.x;
    if (i < N) g_deg[i] = 0;
    if (i < 512) g_stats[i] = 0.0f;
}

__global__ void k_count(const int* __restrict__ row, int E) {
    int e = blockIdx.x * 256 + threadIdx.x;
    if (e < E) atomicAdd(&g_deg[row[e]], 1);
}

__global__ void k_scan(int N) {
    __shared__ int ss[1024];
    int t = threadIdx.x;
    int chunk = (N + 1023) >> 10;
    int lo = t * chunk;
    int hi = min(lo + chunk, N);
    int s = 0;
    for (int i = lo; i < hi; i++) s += g_deg[i];
    ss[t] = s;
    __syncthreads();
    for (int d = 1; d < 1024; d <<= 1) {
        int v = (t >= d) ? ss[t - d] : 0;
        __syncthreads();
        ss[t] += v;
        __syncthreads();
    }
    int run = (t == 0) ? 0 : ss[t - 1];
    for (int i = lo; i < hi; i++) {
        g_off[i] = run;
        g_cur[i] = run;
        run += g_deg[i];
    }
    if (t == 0) g_off[N] = ss[1023];
}

__global__ void k_fill(const int* __restrict__ row, const int* __restrict__ col,
                       const float* __restrict__ ew, int E) {
    int e = blockIdx.x * 256 + threadIdx.x;
    if (e < E) {
        int p = atomicAdd(&g_cur[row[e]], 1);
        g_ccol[p] = col[e];
        g_cw[p]   = ew[e];
    }
}

// ---------------- aggregation: warp-per-node CSR gather --------------------
__global__ void k_agg(const float4* __restrict__ x, float4* __restrict__ out, int N) {
    int warp = (blockIdx.x * blockDim.x + threadIdx.x) >> 5;
    int lane = threadIdx.x & 31;
    if (warp >= N) return;
    int s = g_off[warp], e = g_off[warp + 1];
    float4 a0 = make_float4(0.f, 0.f, 0.f, 0.f);
    float4 a1 = make_float4(0.f, 0.f, 0.f, 0.f);
    int i = s;
    for (; i + 1 < e; i += 2) {
        int   c0 = g_ccol[i];     float w0 = g_cw[i];
        int   c1 = g_ccol[i + 1]; float w1 = g_cw[i + 1];
        float4 v0 = x[(size_t)c0 * 32 + lane];
        float4 v1 = x[(size_t)c1 * 32 + lane];
        a0.x = fmaf(v0.x, w0, a0.x); a0.y = fmaf(v0.y, w0, a0.y);
        a0.z = fmaf(v0.z, w0, a0.z); a0.w = fmaf(v0.w, w0, a0.w);
        a1.x = fmaf(v1.x, w1, a1.x); a1.y = fmaf(v1.y, w1, a1.y);
        a1.z = fmaf(v1.z, w1, a1.z); a1.w = fmaf(v1.w, w1, a1.w);
    }
    if (i < e) {
        int c = g_ccol[i]; float w = g_cw[i];
        float4 v = x[(size_t)c * 32 + lane];
        a0.x = fmaf(v.x, w, a0.x); a0.y = fmaf(v.y, w, a0.y);
        a0.z = fmaf(v.z, w, a0.z); a0.w = fmaf(v.w, w, a0.w);
    }
    a0.x += a1.x; a0.y += a1.y; a0.z += a1.z; a0.w += a1.w;
    out[(size_t)warp * 32 + lane] = a0;
}

// ---------------- GEMM: out[N,128] = A[N,128] @ W[128,128] + bias ----------
// 128-row tile/block, 256 threads, 8x8 microtile via f32x2. smem: A(128x132)+W(128x128)
#define GEMM_SMEM ((128 * 132 + 128 * 128) * 4)

__global__ void __launch_bounds__(256, 1)
k_gemm(const float* __restrict__ A, const float* __restrict__ W,
       const float* __restrict__ bias, float* __restrict__ out, int N) {
    extern __shared__ float smem[];
    float* As = smem;               // 128 rows x 132 (pad)
    float* Ws = smem + 128 * 132;   // 128 x 128
    int t = threadIdx.x;
    int row0 = blockIdx.x << 7;

    for (int i = t; i < 4096; i += 256)
        ((float4*)Ws)[i] = ((const float4*)W)[i];
    for (int i = t; i < 4096; i += 256) {
        int r = i >> 5, c = (i & 31) << 2;
        float4 v = make_float4(0.f, 0.f, 0.f, 0.f);
        if (row0 + r < N) v = *(const float4*)&A[(size_t)(row0 + r) * 128 + c];
        *(float4*)&As[r * 132 + c] = v;
    }
    __syncthreads();

    int tx = t & 15, ty = t >> 4;
    int ra = ty * 4, rb = 64 + ty * 4;
    unsigned long long acc[8][4];
#pragma unroll
    for (int r = 0; r < 8; r++)
#pragma unroll
        for (int c = 0; c < 4; c++) acc[r][c] = 0ull;

#pragma unroll 2
    for (int kk = 0; kk < 128; kk += 4) {
        float4 a4[8];
#pragma unroll
        for (int r = 0; r < 4; r++) {
            a4[r]     = *(const float4*)&As[(ra + r) * 132 + kk];
            a4[r + 4] = *(const float4*)&As[(rb + r) * 132 + kk];
        }
#pragma unroll
        for (int j = 0; j < 4; j++) {
            const float* wr = &Ws[(kk + j) * 128];
            float4 w1 = *(const float4*)&wr[tx * 4];
            float4 w2 = *(const float4*)&wr[64 + tx * 4];
            unsigned long long wp0 = pack2(w1.x, w1.y);
            unsigned long long wp1 = pack2(w1.z, w1.w);
            unsigned long long wp2 = pack2(w2.x, w2.y);
            unsigned long long wp3 = pack2(w2.z, w2.w);
#pragma unroll
            for (int r = 0; r < 8; r++) {
                float av = (j == 0) ? a4[r].x : (j == 1) ? a4[r].y
                         : (j == 2) ? a4[r].z : a4[r].w;
                unsigned long long ap = pack2(av, av);
                acc[r][0] = ffma2(ap, wp0, acc[r][0]);
                acc[r][1] = ffma2(ap, wp1, acc[r][1]);
                acc[r][2] = ffma2(ap, wp2, acc[r][2]);
                acc[r][3] = ffma2(ap, wp3, acc[r][3]);
            }
        }
    }

    float4 bv1 = *(const float4*)&bias[tx * 4];
    float4 bv2 = *(const float4*)&bias[64 + tx * 4];
#pragma unroll
    for (int r = 0; r < 8; r++) {
        int rr = (r < 4) ? (ra + r) : (rb + r - 4);
        int grow = row0 + rr;
        if (grow < N) {
            float2 p0 = unpack2(acc[r][0]), p1 = unpack2(acc[r][1]);
            float2 p2 = unpack2(acc[r][2]), p3 = unpack2(acc[r][3]);
            *(float4*)&out[(size_t)grow * 128 + tx * 4] =
                make_float4(p0.x + bv1.x, p0.y + bv1.y, p1.x + bv1.z, p1.y + bv1.w);
            *(float4*)&out[(size_t)grow * 128 + 64 + tx * 4] =
                make_float4(p2.x + bv2.x, p2.y + bv2.y, p3.x + bv2.z, p3.y + bv2.w);
        }
    }
}

// ---------------- BN stats / finalize / fused BN+poly ----------------------
__global__ void k_stats(const float* __restrict__ X, float* __restrict__ sum,
                        float* __restrict__ sumsq, int N) {
    __shared__ float s1[256], s2[256];
    int t = threadIdx.x;
    size_t total = (size_t)N * 128;
    float a = 0.f, b = 0.f;
    for (size_t i = (size_t)blockIdx.x * 256 + t; i < total;
         i += (size_t)gridDim.x * 256) {
        float v = X[i];
        a += v;
        b = fmaf(v, v, b);
    }
    s1[t] = a; s2[t] = b;
    __syncthreads();
    if (t < 128) {
        atomicAdd(&sum[t],   s1[t] + s1[t + 128]);
        atomicAdd(&sumsq[t], s2[t] + s2[t + 128]);
    }
}

__global__ void k_bnfin(const float* __restrict__ sum, const float* __restrict__ sumsq,
                        const float* __restrict__ gamma, const float* __restrict__ beta,
                        float* __restrict__ scale, float* __restrict__ shift, float invN) {
    int t = threadIdx.x;  // 128 threads
    float m = sum[t] * invN;
    float v = fmaf(-m, m, sumsq[t] * invN);
    float s = gamma[t] * rsqrtf(v + 1e-5f);
    scale[t] = s;
    shift[t] = fmaf(-m, s, beta[t]);
}

__global__ void k_bnpoly(float* __restrict__ X, const float* __restrict__ scale,
                         const float* __restrict__ shift, const float* __restrict__ co,
                         int N) {
    int i = blockIdx.x * 256 + threadIdx.x;
    if (i >= N * 32) return;
    int c4 = i & 31;
    float4 sc = *(const float4*)&scale[c4 << 2];
    float4 sh = *(const float4*)&shift[c4 << 2];
    float c0 = __ldg(&co[0]), c1 = __ldg(&co[1]), c2 = __ldg(&co[2]);
    float c3 = __ldg(&co[3]), cl = __ldg(&co[4]);
    float4 v = ((const float4*)X)[i];
    float x, p;
    x = fmaf(v.x, sc.x, sh.x);
    p = fmaf(cl, x, c3); p = fmaf(p, x, c2); p = fmaf(p, x, c1); v.x = fmaf(p, x, c0);
    x = fmaf(v.y, sc.y, sh.y);
    p = fmaf(cl, x, c3); p = fmaf(p, x, c2); p = fmaf(p, x, c1); v.y = fmaf(p, x, c0);
    x = fmaf(v.z, sc.z, sh.z);
    p = fmaf(cl, x, c3); p = fmaf(p, x, c2); p = fmaf(p, x, c1); v.z = fmaf(p, x, c0);
    x = fmaf(v.w, sc.w, sh.w);
    p = fmaf(cl, x, c3); p = fmaf(p, x, c2); p = fmaf(p, x, c1); v.w = fmaf(p, x, c0);
    ((float4*)X)[i] = v;
}

// ---------------------------------------------------------------------------
extern "C" void kernel_launch(void* const* d_in, const int* in_sizes, int n_in,
                              void* d_out, int out_size) {
    const float* nf     = (const float*)d_in[0];
    const int*   row    = (const int*)  d_in[1];
    const int*   col    = (const int*)  d_in[2];
    const float* ew     = (const float*)d_in[3];
    const float* W1     = (const float*)d_in[4];
    const float* b1     = (const float*)d_in[5];
    const float* W2     = (const float*)d_in[6];
    const float* b2     = (const float*)d_in[7];
    const float* W3     = (const float*)d_in[8];
    const float* b3     = (const float*)d_in[9];
    const float* gamma1 = (const float*)d_in[10];
    const float* beta1  = (const float*)d_in[11];
    const float* gamma2 = (const float*)d_in[12];
    const float* beta2  = (const float*)d_in[13];
    const float* coeffs = (const float*)d_in[14];
    float* out = (float*)d_out;

    int N = in_sizes[0] / 128;
    int E = in_sizes[1];

    cudaFuncSetAttribute(k_gemm, cudaFuncAttributeMaxDynamicSharedMemorySize, GEMM_SMEM);

    void* p;
    cudaGetSymbolAddress(&p, g_agg);   float* agg   = (float*)p;
    cudaGetSymbolAddress(&p, g_act);   float* act   = (float*)p;
    cudaGetSymbolAddress(&p, g_stats); float* stats = (float*)p;
    cudaGetSymbolAddress(&p, g_scale); float* scale = (float*)p;
    cudaGetSymbolAddress(&p, g_shift); float* shift = (float*)p;

    int zb = (N + 255) / 256;
    int eb = (E + 255) / 256;
    int ab = (N + 7) / 8;        // warp-per-node, 8 warps/block
    int gb = (N + 127) / 128;    // gemm 128-row tiles
    int tb = (N * 32 + 255) / 256;
    float invN = 1.0f / (float)N;

    // CSR build
    k_zero <<<zb, 256>>>(N);
    k_count<<<eb, 256>>>(row, E);
    k_scan <<<1, 1024>>>(N);
    k_fill <<<eb, 256>>>(row, col, ew, E);

    // Layer 1
    k_agg   <<<ab, 256>>>((const float4*)nf, (float4*)agg, N);
    k_gemm  <<<gb, 256, GEMM_SMEM>>>(agg, W1, b1, act, N);
    k_stats <<<592, 256>>>(act, stats, stats + 128, N);
    k_bnfin <<<1, 128>>>(stats, stats + 128, gamma1, beta1, scale, shift, invN);
    k_bnpoly<<<tb, 256>>>(act, scale, shift, coeffs, N);

    // Layer 2
    k_agg   <<<ab, 256>>>((const float4*)act, (float4*)agg, N);
    k_gemm  <<<gb, 256, GEMM_SMEM>>>(agg, W2, b2, act, N);
    k_stats <<<592, 256>>>(act, stats + 256, stats + 384, N);
    k_bnfin <<<1, 128>>>(stats + 256, stats + 384, gamma2, beta2, scale, shift, invN);
    k_bnpoly<<<tb, 256>>>(act, scale, shift, coeffs + 5, N);

    // Layer 3 (no BN/poly) -> d_out
    k_agg   <<<ab, 256>>>((const float4*)act, (float4*)agg, N);
    k_gemm  <<<gb, 256, GEMM_SMEM>>>(agg, W3, b3, out, N);
}